// round 5
// baseline (speedup 1.0000x reference)
#include <cuda_runtime.h>
#include <cuda_bf16.h>
#include <cstdint>
#include <math.h>

#define SQ   2048
#define DIM  768
#define NH   12
#define HD   64
#define QKVD 2304
#define FFD  384
#define MAXN 128

// ---------------- scratch (device globals; no allocation allowed) ----------------
__device__ float g_xin[SQ * DIM];
__device__ float g_qkv[SQ * QKVD];
__device__ float g_prj[SQ * DIM];
__device__ float g_x1 [SQ * DIM];
__device__ float g_ff [SQ * DIM];
__device__ int   g_nbr[SQ * MAXN];
__device__ int   g_cnt[SQ];

__device__ __nv_bfloat16 g_xin_h[SQ * DIM],  g_xin_l[SQ * DIM];
__device__ __nv_bfloat16 g_x1_h [SQ * DIM],  g_x1_l [SQ * DIM];
__device__ __nv_bfloat16 g_att_h[SQ * DIM],  g_att_l[SQ * DIM];
__device__ __nv_bfloat16 g_hh_h [SQ * FFD],  g_hh_l [SQ * FFD];
__device__ __nv_bfloat16 g_wq_h [QKVD * DIM], g_wq_l[QKVD * DIM];
__device__ __nv_bfloat16 g_wo_h [DIM * DIM],  g_wo_l[DIM * DIM];
__device__ __nv_bfloat16 g_w1_h [FFD * DIM],  g_w1_l[FFD * DIM];
__device__ __nv_bfloat16 g_w2_h [DIM * FFD],  g_w2_l[DIM * FFD];

// ---------------- PTX helpers (sm_80-era only: safe for compute_103 target) -------
__device__ __forceinline__ uint32_t smem_u32(const void* p) {
    uint32_t a;
    asm("{ .reg .u64 t; cvta.to.shared.u64 t, %1; cvt.u32.u64 %0, t; }" : "=r"(a) : "l"(p));
    return a;
}
#define CP_ASYNC16(dst, src) \
    asm volatile("cp.async.cg.shared.global [%0], [%1], 16;" :: "r"(dst), "l"(src))
#define CP_COMMIT() asm volatile("cp.async.commit_group;" ::: "memory")
#define CP_WAIT(n)  asm volatile("cp.async.wait_group %0;" :: "n"(n) : "memory")

__device__ __forceinline__ void ldsm_x4(uint32_t (&r)[4], uint32_t addr) {
    asm volatile("ldmatrix.sync.aligned.m8n8.x4.shared.b16 {%0,%1,%2,%3}, [%4];"
                 : "=r"(r[0]), "=r"(r[1]), "=r"(r[2]), "=r"(r[3]) : "r"(addr));
}
__device__ __forceinline__ void ldsm_x2(uint32_t (&r)[2], uint32_t addr) {
    asm volatile("ldmatrix.sync.aligned.m8n8.x2.shared.b16 {%0,%1}, [%2];"
                 : "=r"(r[0]), "=r"(r[1]) : "r"(addr));
}
__device__ __forceinline__ void mma_bf16(float (&d)[4], const uint32_t (&a)[4],
                                         const uint32_t (&b)[2]) {
    asm volatile("mma.sync.aligned.m16n8k16.row.col.f32.bf16.bf16.f32 "
                 "{%0,%1,%2,%3}, {%4,%5,%6,%7}, {%8,%9}, {%0,%1,%2,%3};"
                 : "+f"(d[0]), "+f"(d[1]), "+f"(d[2]), "+f"(d[3])
                 : "r"(a[0]), "r"(a[1]), "r"(a[2]), "r"(a[3]), "r"(b[0]), "r"(b[1]));
}

__device__ __forceinline__ void split1(float v, __nv_bfloat16& h, __nv_bfloat16& l) {
    h = __float2bfloat16(v);
    l = __float2bfloat16(v - __bfloat162float(h));
}

// ---------------- block reduce ----------------
__device__ __forceinline__ float block_sum(float v, float* sh) {
    #pragma unroll
    for (int o = 16; o > 0; o >>= 1) v += __shfl_down_sync(0xffffffffu, v, o);
    if ((threadIdx.x & 31) == 0) sh[threadIdx.x >> 5] = v;
    __syncthreads();
    if (threadIdx.x < 32) {
        float t = (threadIdx.x < 8) ? sh[threadIdx.x] : 0.f;
        #pragma unroll
        for (int o = 4; o > 0; o >>= 1) t += __shfl_down_sync(0xffffffffu, t, o);
        if (threadIdx.x == 0) sh[0] = t;
    }
    __syncthreads();
    float r = sh[0];
    __syncthreads();
    return r;
}

// ---------------- fused (a+b) -> LayerNorm (+ optional bf16 split out) ----------------
__global__ void add_ln_kernel(const float* __restrict__ a, const float* __restrict__ b,
                              const float* __restrict__ g, const float* __restrict__ be,
                              float* __restrict__ out,
                              __nv_bfloat16* __restrict__ ohi, __nv_bfloat16* __restrict__ olo) {
    __shared__ float sh[8];
    int row = blockIdx.x;
    const float* pa = a + (size_t)row * DIM;
    const float* pb = b + (size_t)row * DIM;
    float v[3]; float s = 0.f;
    #pragma unroll
    for (int i = 0; i < 3; i++) { int c = threadIdx.x + i * 256; v[i] = pa[c] + pb[c]; s += v[i]; }
    float mu = block_sum(s, sh) * (1.f / DIM);
    float s2 = 0.f;
    #pragma unroll
    for (int i = 0; i < 3; i++) { float d = v[i] - mu; s2 += d * d; }
    float var = block_sum(s2, sh) * (1.f / DIM);
    float rstd = rsqrtf(var + 1e-5f);
    #pragma unroll
    for (int i = 0; i < 3; i++) {
        int c = threadIdx.x + i * 256;
        float y = (v[i] - mu) * rstd * g[c] + be[c];
        out[(size_t)row * DIM + c] = y;
        if (ohi) {
            __nv_bfloat16 h, l; split1(y, h, l);
            ohi[(size_t)row * DIM + c] = h;
            olo[(size_t)row * DIM + c] = l;
        }
    }
}

// ---------------- fused fp32 -> bf16 split for 4 weight matrices ----------------
__global__ void split4_kernel(const float* __restrict__ s0, __nv_bfloat16* h0, __nv_bfloat16* l0, int n0,
                              const float* __restrict__ s1, __nv_bfloat16* h1, __nv_bfloat16* l1, int n1,
                              const float* __restrict__ s2, __nv_bfloat16* h2, __nv_bfloat16* l2, int n2,
                              const float* __restrict__ s3, __nv_bfloat16* h3, __nv_bfloat16* l3, int n3) {
    const float* x; __nv_bfloat16 *hi, *lo; int n4;
    switch (blockIdx.y) {
        case 0: x = s0; hi = h0; lo = l0; n4 = n0; break;
        case 1: x = s1; hi = h1; lo = l1; n4 = n1; break;
        case 2: x = s2; hi = h2; lo = l2; n4 = n2; break;
        default: x = s3; hi = h3; lo = l3; n4 = n3; break;
    }
    int i = blockIdx.x * 256 + threadIdx.x;
    if (i < n4) {
        float4 v = ((const float4*)x)[i];
        __nv_bfloat16 a0, b0, a1, b1, a2, b2, a3, b3;
        split1(v.x, a0, b0); split1(v.y, a1, b1); split1(v.z, a2, b2); split1(v.w, a3, b3);
        __nv_bfloat162* ph = (__nv_bfloat162*)(hi + (size_t)i * 4);
        __nv_bfloat162* pl = (__nv_bfloat162*)(lo + (size_t)i * 4);
        ph[0] = __nv_bfloat162(a0, a1); ph[1] = __nv_bfloat162(a2, a3);
        pl[0] = __nv_bfloat162(b0, b1); pl[1] = __nv_bfloat162(b2, b3);
    }
}

// ---------------- adjacency -> per-query neighbor lists ----------------
__global__ void build_nbr_kernel(const int* __restrict__ adj) {
    int q = blockIdx.x;
    __shared__ int cnt;
    if (threadIdx.x == 0) cnt = 0;
    __syncthreads();
    for (int k = threadIdx.x; k < SQ; k += blockDim.x) {
        if (adj[(size_t)q * SQ + k] != 0) {
            int p = atomicAdd(&cnt, 1);
            if (p < MAXN) g_nbr[q * MAXN + p] = k;
        }
    }
    __syncthreads();
    if (threadIdx.x == 0) g_cnt[q] = cnt < MAXN ? cnt : MAXN;
}

// ---------------- sparse attention (writes bf16-split output) ----------------
__global__ void attn_kernel() {
    int q    = blockIdx.x;
    int tid  = threadIdx.x;          // 192 threads
    int head = tid >> 4;
    int l    = tid & 15;
    __shared__ float qv[DIM];
    __shared__ float sc[NH][MAXN];
    __shared__ int   nbr[MAXN];

    int n = g_cnt[q];
    for (int i = tid; i < DIM; i += 192) qv[i] = g_qkv[(size_t)q * QKVD + i];
    for (int i = tid; i < n;   i += 192) nbr[i] = g_nbr[q * MAXN + i];
    __syncthreads();

    const float4 q4 = *(const float4*)(qv + head * HD + l * 4);
    const size_t koff = DIM + head * HD + l * 4;
    int j = 0;
    for (; j + 1 < n; j += 2) {
        const float4 ka = *(const float4*)(g_qkv + (size_t)nbr[j]     * QKVD + koff);
        const float4 kb = *(const float4*)(g_qkv + (size_t)nbr[j + 1] * QKVD + koff);
        float sa = q4.x * ka.x + q4.y * ka.y + q4.z * ka.z + q4.w * ka.w;
        float sb = q4.x * kb.x + q4.y * kb.y + q4.z * kb.z + q4.w * kb.w;
        #pragma unroll
        for (int o = 8; o > 0; o >>= 1) {
            sa += __shfl_down_sync(0xffffffffu, sa, o, 16);
            sb += __shfl_down_sync(0xffffffffu, sb, o, 16);
        }
        if (l == 0) { sc[head][j] = sa * 0.125f; sc[head][j + 1] = sb * 0.125f; }
    }
    if (j < n) {
        const float4 ka = *(const float4*)(g_qkv + (size_t)nbr[j] * QKVD + koff);
        float sa = q4.x * ka.x + q4.y * ka.y + q4.z * ka.z + q4.w * ka.w;
        #pragma unroll
        for (int o = 8; o > 0; o >>= 1) sa += __shfl_down_sync(0xffffffffu, sa, o, 16);
        if (l == 0) sc[head][j] = sa * 0.125f;
    }
    __syncwarp();

    float m = -INFINITY;
    for (int i = l; i < n; i += 16) m = fmaxf(m, sc[head][i]);
    #pragma unroll
    for (int o = 8; o > 0; o >>= 1) m = fmaxf(m, __shfl_xor_sync(0xffffffffu, m, o, 16));
    float sum = 0.f;
    for (int i = l; i < n; i += 16) { float e = __expf(sc[head][i] - m); sc[head][i] = e; sum += e; }
    #pragma unroll
    for (int o = 8; o > 0; o >>= 1) sum += __shfl_xor_sync(0xffffffffu, sum, o, 16);
    float inv = 1.f / sum;
    __syncwarp();

    const size_t voff = 2 * DIM + head * HD + l * 4;
    float4 acc0 = make_float4(0.f, 0.f, 0.f, 0.f);
    float4 acc1 = make_float4(0.f, 0.f, 0.f, 0.f);
    j = 0;
    for (; j + 1 < n; j += 2) {
        float pa = sc[head][j] * inv, pb = sc[head][j + 1] * inv;
        const float4 va = *(const float4*)(g_qkv + (size_t)nbr[j]     * QKVD + voff);
        const float4 vb = *(const float4*)(g_qkv + (size_t)nbr[j + 1] * QKVD + voff);
        acc0.x += pa * va.x; acc0.y += pa * va.y; acc0.z += pa * va.z; acc0.w += pa * va.w;
        acc1.x += pb * vb.x; acc1.y += pb * vb.y; acc1.z += pb * vb.z; acc1.w += pb * vb.w;
    }
    if (j < n) {
        float pa = sc[head][j] * inv;
        const float4 va = *(const float4*)(g_qkv + (size_t)nbr[j] * QKVD + voff);
        acc0.x += pa * va.x; acc0.y += pa * va.y; acc0.z += pa * va.z; acc0.w += pa * va.w;
    }
    acc0.x += acc1.x; acc0.y += acc1.y; acc0.z += acc1.z; acc0.w += acc1.w;

    size_t base = (size_t)q * DIM + head * HD + l * 4;
    __nv_bfloat16 h0, l0, h1, l1, h2, l2, h3, l3;
    split1(acc0.x, h0, l0); split1(acc0.y, h1, l1); split1(acc0.z, h2, l2); split1(acc0.w, h3, l3);
    __nv_bfloat162* ph = (__nv_bfloat162*)(g_att_h + base);
    __nv_bfloat162* pl = (__nv_bfloat162*)(g_att_l + base);
    ph[0] = __nv_bfloat162(h0, h1); ph[1] = __nv_bfloat162(h2, h3);
    pl[0] = __nv_bfloat162(l0, l1); pl[1] = __nv_bfloat162(l2, l3);
}

// ---------------- bf16-split GEMM via mma.sync: C = A*B^T + bias ----------------
// 3-stage cp.async pipeline, ONE __syncthreads per k-iteration.
#define RSB    80                    // padded row stride bytes: conflict-free ldmatrix
#define MATB   (128 * RSB)
#define STAGEB (4 * MATB)            // 40960
#define NSTAGE 3
#define GEMM_SMEM (NSTAGE * STAGEB)  // 122880

template <bool RELU, bool BF16OUT>
__global__ void __launch_bounds__(256, 1)
gemm_mma(const __nv_bfloat16* __restrict__ Ahi, const __nv_bfloat16* __restrict__ Alo,
         const __nv_bfloat16* __restrict__ Bhi, const __nv_bfloat16* __restrict__ Blo,
         const float* __restrict__ bias,
         float* __restrict__ C, __nv_bfloat16* __restrict__ Chi, __nv_bfloat16* __restrict__ Clo,
         int N, int K) {
    extern __shared__ char dsm[];
    const uint32_t sb = smem_u32(dsm);

    const int tid = threadIdx.x, wid = tid >> 5, lane = tid & 31;
    const int bm = blockIdx.y, bn = blockIdx.x;
    const int wm = wid >> 2, wn = wid & 3;
    const int m0 = wm * 64, n0 = wn * 32;

    const __nv_bfloat16* gp[4] = {
        Ahi + (size_t)(bm * 128) * K, Alo + (size_t)(bm * 128) * K,
        Bhi + (size_t)(bn * 128) * K, Blo + (size_t)(bn * 128) * K };

    const int ldrow = tid >> 2, ldc16 = tid & 3;

    float acc[4][4][4];
    #pragma unroll
    for (int i = 0; i < 4; i++)
        #pragma unroll
        for (int j = 0; j < 4; j++)
            #pragma unroll
            for (int v = 0; v < 4; v++) acc[i][j][v] = 0.f;

    const int KT = K >> 5;

    auto load_stage = [&](int s, int kt) {
        uint32_t base = sb + s * STAGEB;
        #pragma unroll
        for (int m = 0; m < 4; m++) {
            const __nv_bfloat16* g = gp[m] + kt * 32;
            #pragma unroll
            for (int j = 0; j < 2; j++) {
                int row = ldrow + j * 64;
                CP_ASYNC16(base + m * MATB + row * RSB + ldc16 * 16,
                           g + (size_t)row * K + ldc16 * 8);
            }
        }
        CP_COMMIT();
    };

    load_stage(0, 0);
    if (KT > 1) load_stage(1, 1); else CP_COMMIT();

    const int arow = lane & 15, ahalf = lane >> 4;
    const int brow = lane & 7,  bhalf = (lane >> 3) & 1;

    int stage = 0;
    for (int kt = 0; kt < KT; kt++) {
        CP_WAIT(1);
        __syncthreads();
        if (kt + 2 < KT) {
            int s = stage + 2; if (s >= NSTAGE) s -= NSTAGE;
            load_stage(s, kt + 2);
        } else CP_COMMIT();

        uint32_t base = sb + stage * STAGEB;
        #pragma unroll
        for (int ks = 0; ks < 2; ks++) {
            uint32_t ah[4][4], al[4][4], bh[4][2], bl[4][2];
            #pragma unroll
            for (int im = 0; im < 4; im++) {
                uint32_t off = (m0 + im * 16 + arow) * RSB + ks * 32 + ahalf * 16;
                ldsm_x4(ah[im], base + 0 * MATB + off);
                ldsm_x4(al[im], base + 1 * MATB + off);
            }
            #pragma unroll
            for (int in = 0; in < 4; in++) {
                uint32_t off = (n0 + in * 8 + brow) * RSB + ks * 32 + bhalf * 16;
                ldsm_x2(bh[in], base + 2 * MATB + off);
                ldsm_x2(bl[in], base + 3 * MATB + off);
            }
            #pragma unroll
            for (int im = 0; im < 4; im++)
                #pragma unroll
                for (int in = 0; in < 4; in++) {
                    mma_bf16(acc[im][in], ah[im], bh[in]);
                    mma_bf16(acc[im][in], ah[im], bl[in]);
                    mma_bf16(acc[im][in], al[im], bh[in]);
                }
        }
        if (++stage == NSTAGE) stage = 0;
    }

    const int crow = lane >> 2, ccol = (lane & 3) * 2;
    #pragma unroll
    for (int im = 0; im < 4; im++) {
        #pragma unroll
        for (int in = 0; in < 4; in++) {
            int col = bn * 128 + n0 + in * 8 + ccol;
            float b0 = bias[col], b1 = bias[col + 1];
            #pragma unroll
            for (int half = 0; half < 2; half++) {
                int row = bm * 128 + m0 + im * 16 + crow + half * 8;
                float v0 = acc[im][in][half * 2 + 0] + b0;
                float v1 = acc[im][in][half * 2 + 1] + b1;
                if (RELU) { v0 = fmaxf(v0, 0.f); v1 = fmaxf(v1, 0.f); }
                size_t go = (size_t)row * N + col;
                if (BF16OUT) {
                    __nv_bfloat16 h0, l0, h1, l1;
                    split1(v0, h0, l0); split1(v1, h1, l1);
                    *(__nv_bfloat162*)(Chi + go) = __nv_bfloat162(h0, h1);
                    *(__nv_bfloat162*)(Clo + go) = __nv_bfloat162(l0, l1);
                } else {
                    *(float2*)(C + go) = make_float2(v0, v1);
                }
            }
        }
    }
}

// ---------------- 64x64-tile variant (128 threads, 2x2 warps of 32x32), 3-stage ----
#define MATB64   (64 * RSB)          // 5120
#define STAGEB64 (4 * MATB64)        // 20480
#define GEMM_SMEM64 (NSTAGE * STAGEB64)  // 61440

template <bool RELU, bool BF16OUT>
__global__ void __launch_bounds__(128, 3)
gemm_mma64(const __nv_bfloat16* __restrict__ Ahi, const __nv_bfloat16* __restrict__ Alo,
           const __nv_bfloat16* __restrict__ Bhi, const __nv_bfloat16* __restrict__ Blo,
           const float* __restrict__ bias,
           float* __restrict__ C, __nv_bfloat16* __restrict__ Chi, __nv_bfloat16* __restrict__ Clo,
           int N, int K) {
    extern __shared__ char dsm[];
    const uint32_t sb = smem_u32(dsm);

    const int tid = threadIdx.x, wid = tid >> 5, lane = tid & 31;
    const int bm = blockIdx.y, bn = blockIdx.x;
    const int wm = wid >> 1, wn = wid & 1;
    const int m0 = wm * 32, n0 = wn * 32;

    const __nv_bfloat16* gp[4] = {
        Ahi + (size_t)(bm * 64) * K, Alo + (size_t)(bm * 64) * K,
        Bhi + (size_t)(bn * 64) * K, Blo + (size_t)(bn * 64) * K };

    const int ldrow = tid >> 2, ldc16 = tid & 3;

    float acc[2][4][4];
    #pragma unroll
    for (int i = 0; i < 2; i++)
        #pragma unroll
        for (int j = 0; j < 4; j++)
            #pragma unroll
            for (int v = 0; v < 4; v++) acc[i][j][v] = 0.f;

    const int KT = K >> 5;

    auto load_stage = [&](int s, int kt) {
        uint32_t base = sb + s * STAGEB64;
        #pragma unroll
        for (int m = 0; m < 4; m++) {
            const __nv_bfloat16* g = gp[m] + kt * 32;
            #pragma unroll
            for (int j = 0; j < 2; j++) {
                int row = ldrow + j * 32;
                CP_ASYNC16(base + m * MATB64 + row * RSB + ldc16 * 16,
                           g + (size_t)row * K + ldc16 * 8);
            }
        }
        CP_COMMIT();
    };

    load_stage(0, 0);
    if (KT > 1) load_stage(1, 1); else CP_COMMIT();

    const int arow = lane & 15, ahalf = lane >> 4;
    const int brow = lane & 7,  bhalf = (lane >> 3) & 1;

    int stage = 0;
    for (int kt = 0; kt < KT; kt++) {
        CP_WAIT(1);
        __syncthreads();
        if (kt + 2 < KT) {
            int s = stage + 2; if (s >= NSTAGE) s -= NSTAGE;
            load_stage(s, kt + 2);
        } else CP_COMMIT();

        uint32_t base = sb + stage * STAGEB64;
        #pragma unroll
        for (int ks = 0; ks < 2; ks++) {
            uint32_t ah[2][4], al[2][4], bh[4][2], bl[4][2];
            #pragma unroll
            for (int im = 0; im < 2; im++) {
                uint32_t off = (m0 + im * 16 + arow) * RSB + ks * 32 + ahalf * 16;
                ldsm_x4(ah[im], base + 0 * MATB64 + off);
                ldsm_x4(al[im], base + 1 * MATB64 + off);
            }
            #pragma unroll
            for (int in = 0; in < 4; in++) {
                uint32_t off = (n0 + in * 8 + brow) * RSB + ks * 32 + bhalf * 16;
                ldsm_x2(bh[in], base + 2 * MATB64 + off);
                ldsm_x2(bl[in], base + 3 * MATB64 + off);
            }
            #pragma unroll
            for (int im = 0; im < 2; im++)
                #pragma unroll
                for (int in = 0; in < 4; in++) {
                    mma_bf16(acc[im][in], ah[im], bh[in]);
                    mma_bf16(acc[im][in], ah[im], bl[in]);
                    mma_bf16(acc[im][in], al[im], bh[in]);
                }
        }
        if (++stage == NSTAGE) stage = 0;
    }

    const int crow = lane >> 2, ccol = (lane & 3) * 2;
    #pragma unroll
    for (int im = 0; im < 2; im++) {
        #pragma unroll
        for (int in = 0; in < 4; in++) {
            int col = bn * 64 + n0 + in * 8 + ccol;
            float b0 = bias[col], b1 = bias[col + 1];
            #pragma unroll
            for (int half = 0; half < 2; half++) {
                int row = bm * 64 + m0 + im * 16 + crow + half * 8;
                float v0 = acc[im][in][half * 2 + 0] + b0;
                float v1 = acc[im][in][half * 2 + 1] + b1;
                if (RELU) { v0 = fmaxf(v0, 0.f); v1 = fmaxf(v1, 0.f); }
                size_t go = (size_t)row * N + col;
                if (BF16OUT) {
                    __nv_bfloat16 h0, l0, h1, l1;
                    split1(v0, h0, l0); split1(v1, h1, l1);
                    *(__nv_bfloat162*)(Chi + go) = __nv_bfloat162(h0, h1);
                    *(__nv_bfloat162*)(Clo + go) = __nv_bfloat162(l0, l1);
                } else {
                    *(float2*)(C + go) = make_float2(v0, v1);
                }
            }
        }
    }
}

// ---------------- launch ----------------
extern "C" void kernel_launch(void* const* d_in, const int* in_sizes, int n_in,
                              void* d_out, int out_size) {
    const float* exp_e = (const float*)d_in[0];
    const float* per_e = (const float*)d_in[1];
    const float* ipw   = (const float*)d_in[2];
    const float* ipb   = (const float*)d_in[3];
    const float* opw   = (const float*)d_in[4];
    const float* opb   = (const float*)d_in[5];
    const float* ln0g  = (const float*)d_in[6];
    const float* ln0b  = (const float*)d_in[7];
    const float* ln1g  = (const float*)d_in[8];
    const float* ln1b  = (const float*)d_in[9];
    const float* ln2g  = (const float*)d_in[10];
    const float* ln2b  = (const float*)d_in[11];
    const float* w1    = (const float*)d_in[12];
    const float* b1    = (const float*)d_in[13];
    const float* w2    = (const float*)d_in[14];
    const float* b2    = (const float*)d_in[15];
    const int*   adj   = (const int*)d_in[16];
    float* out = (float*)d_out;

    float *xin, *qkv, *prj, *x1, *ff;
    cudaGetSymbolAddress((void**)&xin, g_xin);
    cudaGetSymbolAddress((void**)&qkv, g_qkv);
    cudaGetSymbolAddress((void**)&prj, g_prj);
    cudaGetSymbolAddress((void**)&x1,  g_x1);
    cudaGetSymbolAddress((void**)&ff,  g_ff);
    __nv_bfloat16 *xinh, *xinl, *x1h, *x1l, *atth, *attl, *hhh, *hhl;
    __nv_bfloat16 *wqh, *wql, *woh, *wol, *w1h, *w1l, *w2h, *w2l;
    cudaGetSymbolAddress((void**)&xinh, g_xin_h); cudaGetSymbolAddress((void**)&xinl, g_xin_l);
    cudaGetSymbolAddress((void**)&x1h,  g_x1_h);  cudaGetSymbolAddress((void**)&x1l,  g_x1_l);
    cudaGetSymbolAddress((void**)&atth, g_att_h); cudaGetSymbolAddress((void**)&attl, g_att_l);
    cudaGetSymbolAddress((void**)&hhh,  g_hh_h);  cudaGetSymbolAddress((void**)&hhl,  g_hh_l);
    cudaGetSymbolAddress((void**)&wqh,  g_wq_h);  cudaGetSymbolAddress((void**)&wql,  g_wq_l);
    cudaGetSymbolAddress((void**)&woh,  g_wo_h);  cudaGetSymbolAddress((void**)&wol,  g_wo_l);
    cudaGetSymbolAddress((void**)&w1h,  g_w1_h);  cudaGetSymbolAddress((void**)&w1l,  g_w1_l);
    cudaGetSymbolAddress((void**)&w2h,  g_w2_h);  cudaGetSymbolAddress((void**)&w2l,  g_w2_l);

    cudaFuncSetAttribute(gemm_mma<false, false>, cudaFuncAttributeMaxDynamicSharedMemorySize, GEMM_SMEM);
    cudaFuncSetAttribute(gemm_mma64<false, false>, cudaFuncAttributeMaxDynamicSharedMemorySize, GEMM_SMEM64);
    cudaFuncSetAttribute(gemm_mma64<true,  true >, cudaFuncAttributeMaxDynamicSharedMemorySize, GEMM_SMEM64);

    // all four weight splits in one launch
    split4_kernel<<<dim3(1728, 4), 256>>>(
        ipw, wqh, wql, QKVD * DIM / 4,
        opw, woh, wol, DIM * DIM / 4,
        w1,  w1h, w1l, FFD * DIM / 4,
        w2,  w2h, w2l, DIM * FFD / 4);
    // neighbor lists
    build_nbr_kernel<<<SQ, 256>>>(adj);
    // x_in = LN0(exp + pert), + bf16 split
    add_ln_kernel<<<SQ, 256>>>(exp_e, per_e, ln0g, ln0b, xin, xinh, xinl);
    // qkv = x_in @ ipw^T + ipb   (288 CTAs, 128x128)
    gemm_mma<false, false><<<dim3(QKVD / 128, SQ / 128), 256, GEMM_SMEM>>>(
        xinh, xinl, wqh, wql, ipb, qkv, nullptr, nullptr, QKVD, DIM);
    // sparse attention -> bf16 split att
    attn_kernel<<<SQ, 192>>>();
    // prj = att @ opw^T + opb   (384 CTAs, 64x64)
    gemm_mma64<false, false><<<dim3(DIM / 64, SQ / 64), 128, GEMM_SMEM64>>>(
        atth, attl, woh, wol, opb, prj, nullptr, nullptr, DIM, DIM);
    // x1 = LN1(prj + xin), + split
    add_ln_kernel<<<SQ, 256>>>(prj, xin, ln1g, ln1b, x1, x1h, x1l);
    // hh = relu(x1 @ w1^T + b1) -> bf16 split   (192 CTAs, 64x64)
    gemm_mma64<true, true><<<dim3(FFD / 64, SQ / 64), 128, GEMM_SMEM64>>>(
        x1h, x1l, w1h, w1l, b1, nullptr, hhh, hhl, FFD, DIM);
    // ff = hh @ w2^T + b2   (384 CTAs, 64x64)
    gemm_mma64<false, false><<<dim3(DIM / 64, SQ / 64), 128, GEMM_SMEM64>>>(
        hhh, hhl, w2h, w2l, b2, ff, nullptr, nullptr, DIM, FFD);
    // out = LN2(x1 + ff)
    add_ln_kernel<<<SQ, 256>>>(x1, ff, ln2g, ln2b, out, nullptr, nullptr);
}

// round 6
// speedup vs baseline: 1.3088x; 1.3088x over previous
#include <cuda_runtime.h>
#include <cstdint>
#include <math.h>

#define SQ   2048
#define DIM  768
#define NH   12
#define HD   64
#define QKVD 2304
#define FFD  384
#define MAXN 128

// ---------------- scratch (device globals; no allocation allowed) ----------------
__device__ float g_xin[SQ * DIM];     // LN0 output (tf32-rounded)
__device__ float g_qkv[SQ * QKVD];
__device__ float g_att[SQ * DIM];     // attention output (tf32-rounded)
__device__ float g_prj[SQ * DIM];
__device__ float g_x1 [SQ * DIM];     // LN1 output (tf32-rounded)
__device__ float g_hh [SQ * FFD];     // relu(ff1) (tf32-rounded)
__device__ float g_ff [SQ * DIM];
__device__ float g_wq [QKVD * DIM];   // tf32-rounded weights
__device__ float g_wo [DIM * DIM];
__device__ float g_w1 [FFD * DIM];
__device__ float g_w2 [DIM * FFD];
__device__ int   g_nbr[SQ * MAXN];
__device__ int   g_cnt[SQ];

// ---------------- PTX helpers (sm_80-era only) ----------------
__device__ __forceinline__ uint32_t smem_u32(const void* p) {
    uint32_t a;
    asm("{ .reg .u64 t; cvta.to.shared.u64 t, %1; cvt.u32.u64 %0, t; }" : "=r"(a) : "l"(p));
    return a;
}
#define CP_ASYNC16(dst, src) \
    asm volatile("cp.async.cg.shared.global [%0], [%1], 16;" :: "r"(dst), "l"(src))
#define CP_COMMIT() asm volatile("cp.async.commit_group;" ::: "memory")
#define CP_WAIT(n)  asm volatile("cp.async.wait_group %0;" :: "n"(n) : "memory")

__device__ __forceinline__ void ldsm_x4(uint32_t (&r)[4], uint32_t addr) {
    asm volatile("ldmatrix.sync.aligned.m8n8.x4.shared.b16 {%0,%1,%2,%3}, [%4];"
                 : "=r"(r[0]), "=r"(r[1]), "=r"(r[2]), "=r"(r[3]) : "r"(addr));
}
__device__ __forceinline__ void ldsm_x2(uint32_t (&r)[2], uint32_t addr) {
    asm volatile("ldmatrix.sync.aligned.m8n8.x2.shared.b16 {%0,%1}, [%2];"
                 : "=r"(r[0]), "=r"(r[1]) : "r"(addr));
}
__device__ __forceinline__ void mma_tf32(float (&d)[4], const uint32_t (&a)[4],
                                         const uint32_t (&b)[2]) {
    asm volatile("mma.sync.aligned.m16n8k8.row.col.f32.tf32.tf32.f32 "
                 "{%0,%1,%2,%3}, {%4,%5,%6,%7}, {%8,%9}, {%0,%1,%2,%3};"
                 : "+f"(d[0]), "+f"(d[1]), "+f"(d[2]), "+f"(d[3])
                 : "r"(a[0]), "r"(a[1]), "r"(a[2]), "r"(a[3]), "r"(b[0]), "r"(b[1]));
}
__device__ __forceinline__ float rtf32(float v) {
    uint32_t y;
    asm("cvt.rna.tf32.f32 %0, %1;" : "=r"(y) : "f"(v));
    return __uint_as_float(y);
}

// ---------------- block reduce ----------------
__device__ __forceinline__ float block_sum(float v, float* sh) {
    #pragma unroll
    for (int o = 16; o > 0; o >>= 1) v += __shfl_down_sync(0xffffffffu, v, o);
    if ((threadIdx.x & 31) == 0) sh[threadIdx.x >> 5] = v;
    __syncthreads();
    if (threadIdx.x < 32) {
        float t = (threadIdx.x < 8) ? sh[threadIdx.x] : 0.f;
        #pragma unroll
        for (int o = 4; o > 0; o >>= 1) t += __shfl_down_sync(0xffffffffu, t, o);
        if (threadIdx.x == 0) sh[0] = t;
    }
    __syncthreads();
    float r = sh[0];
    __syncthreads();
    return r;
}

// ---------------- fused (a+b) -> LayerNorm (optional tf32 rounding) ----------------
__global__ void add_ln_kernel(const float* __restrict__ a, const float* __restrict__ b,
                              const float* __restrict__ g, const float* __restrict__ be,
                              float* __restrict__ out, int rnd) {
    __shared__ float sh[8];
    int row = blockIdx.x;
    const float* pa = a + (size_t)row * DIM;
    const float* pb = b + (size_t)row * DIM;
    float v[3]; float s = 0.f;
    #pragma unroll
    for (int i = 0; i < 3; i++) { int c = threadIdx.x + i * 256; v[i] = pa[c] + pb[c]; s += v[i]; }
    float mu = block_sum(s, sh) * (1.f / DIM);
    float s2 = 0.f;
    #pragma unroll
    for (int i = 0; i < 3; i++) { float d = v[i] - mu; s2 += d * d; }
    float var = block_sum(s2, sh) * (1.f / DIM);
    float rstd = rsqrtf(var + 1e-5f);
    #pragma unroll
    for (int i = 0; i < 3; i++) {
        int c = threadIdx.x + i * 256;
        float y = (v[i] - mu) * rstd * g[c] + be[c];
        out[(size_t)row * DIM + c] = rnd ? rtf32(y) : y;
    }
}

// ---------------- weight rounding to tf32 (4 matrices, one launch) ----------------
__global__ void round4_kernel(const float* __restrict__ s0, float* d0, int n0,
                              const float* __restrict__ s1, float* d1, int n1,
                              const float* __restrict__ s2, float* d2, int n2,
                              const float* __restrict__ s3, float* d3, int n3) {
    const float* x; float* d; int n4;
    switch (blockIdx.y) {
        case 0: x = s0; d = d0; n4 = n0; break;
        case 1: x = s1; d = d1; n4 = n1; break;
        case 2: x = s2; d = d2; n4 = n2; break;
        default: x = s3; d = d3; n4 = n3; break;
    }
    int i = blockIdx.x * 256 + threadIdx.x;
    if (i < n4) {
        float4 v = ((const float4*)x)[i];
        v.x = rtf32(v.x); v.y = rtf32(v.y); v.z = rtf32(v.z); v.w = rtf32(v.w);
        ((float4*)d)[i] = v;
    }
}

// ---------------- adjacency -> per-query neighbor lists ----------------
__global__ void build_nbr_kernel(const int* __restrict__ adj) {
    int q = blockIdx.x;
    __shared__ int cnt;
    if (threadIdx.x == 0) cnt = 0;
    __syncthreads();
    for (int k = threadIdx.x; k < SQ; k += blockDim.x) {
        if (adj[(size_t)q * SQ + k] != 0) {
            int p = atomicAdd(&cnt, 1);
            if (p < MAXN) g_nbr[q * MAXN + p] = k;
        }
    }
    __syncthreads();
    if (threadIdx.x == 0) g_cnt[q] = cnt < MAXN ? cnt : MAXN;
}

// ---------------- sparse attention (tf32-rounded output) ----------------
__global__ void attn_kernel() {
    int q    = blockIdx.x;
    int tid  = threadIdx.x;          // 192 threads
    int head = tid >> 4;
    int l    = tid & 15;
    __shared__ float qv[DIM];
    __shared__ float sc[NH][MAXN];
    __shared__ int   nbr[MAXN];

    int n = g_cnt[q];
    for (int i = tid; i < DIM; i += 192) qv[i] = g_qkv[(size_t)q * QKVD + i];
    for (int i = tid; i < n;   i += 192) nbr[i] = g_nbr[q * MAXN + i];
    __syncthreads();

    const float4 q4 = *(const float4*)(qv + head * HD + l * 4);
    const size_t koff = DIM + head * HD + l * 4;
    int j = 0;
    for (; j + 1 < n; j += 2) {
        const float4 ka = *(const float4*)(g_qkv + (size_t)nbr[j]     * QKVD + koff);
        const float4 kb = *(const float4*)(g_qkv + (size_t)nbr[j + 1] * QKVD + koff);
        float sa = q4.x * ka.x + q4.y * ka.y + q4.z * ka.z + q4.w * ka.w;
        float sb = q4.x * kb.x + q4.y * kb.y + q4.z * kb.z + q4.w * kb.w;
        #pragma unroll
        for (int o = 8; o > 0; o >>= 1) {
            sa += __shfl_down_sync(0xffffffffu, sa, o, 16);
            sb += __shfl_down_sync(0xffffffffu, sb, o, 16);
        }
        if (l == 0) { sc[head][j] = sa * 0.125f; sc[head][j + 1] = sb * 0.125f; }
    }
    if (j < n) {
        const float4 ka = *(const float4*)(g_qkv + (size_t)nbr[j] * QKVD + koff);
        float sa = q4.x * ka.x + q4.y * ka.y + q4.z * ka.z + q4.w * ka.w;
        #pragma unroll
        for (int o = 8; o > 0; o >>= 1) sa += __shfl_down_sync(0xffffffffu, sa, o, 16);
        if (l == 0) sc[head][j] = sa * 0.125f;
    }
    __syncwarp();

    float m = -INFINITY;
    for (int i = l; i < n; i += 16) m = fmaxf(m, sc[head][i]);
    #pragma unroll
    for (int o = 8; o > 0; o >>= 1) m = fmaxf(m, __shfl_xor_sync(0xffffffffu, m, o, 16));
    float sum = 0.f;
    for (int i = l; i < n; i += 16) { float e = __expf(sc[head][i] - m); sc[head][i] = e; sum += e; }
    #pragma unroll
    for (int o = 8; o > 0; o >>= 1) sum += __shfl_xor_sync(0xffffffffu, sum, o, 16);
    float inv = 1.f / sum;
    __syncwarp();

    const size_t voff = 2 * DIM + head * HD + l * 4;
    float4 acc0 = make_float4(0.f, 0.f, 0.f, 0.f);
    float4 acc1 = make_float4(0.f, 0.f, 0.f, 0.f);
    j = 0;
    for (; j + 1 < n; j += 2) {
        float pa = sc[head][j] * inv, pb = sc[head][j + 1] * inv;
        const float4 va = *(const float4*)(g_qkv + (size_t)nbr[j]     * QKVD + voff);
        const float4 vb = *(const float4*)(g_qkv + (size_t)nbr[j + 1] * QKVD + voff);
        acc0.x += pa * va.x; acc0.y += pa * va.y; acc0.z += pa * va.z; acc0.w += pa * va.w;
        acc1.x += pb * vb.x; acc1.y += pb * vb.y; acc1.z += pb * vb.z; acc1.w += pb * vb.w;
    }
    if (j < n) {
        float pa = sc[head][j] * inv;
        const float4 va = *(const float4*)(g_qkv + (size_t)nbr[j] * QKVD + voff);
        acc0.x += pa * va.x; acc0.y += pa * va.y; acc0.z += pa * va.z; acc0.w += pa * va.w;
    }
    float4 r;
    r.x = rtf32(acc0.x + acc1.x); r.y = rtf32(acc0.y + acc1.y);
    r.z = rtf32(acc0.z + acc1.z); r.w = rtf32(acc0.w + acc1.w);
    *(float4*)(g_att + (size_t)q * DIM + head * HD + l * 4) = r;
}

// ---------------- tf32 GEMM via mma.sync m16n8k8: C = A*B^T + bias --------------
// Inputs pre-rounded to tf32. Row stride 144B (36 floats): rows hit banks 4r..4r+3
// -> conflict-free ldmatrix. BK=32 (4 k-steps of 8).
#define RSB      144
#define MATB     (128 * RSB)              // 18432
#define STAGEB   (2 * MATB)               // 36864 (A + B)
#define NSTAGE   3
#define GEMM_SMEM (NSTAGE * STAGEB)       // 110592 -> 2 CTAs/SM

__global__ void __launch_bounds__(256, 2)
gemm_t128(const float* __restrict__ A, const float* __restrict__ B,
          const float* __restrict__ bias, float* __restrict__ C, int N, int K) {
    extern __shared__ char dsm[];
    const uint32_t sb = smem_u32(dsm);

    const int tid = threadIdx.x, wid = tid >> 5, lane = tid & 31;
    const int bm = blockIdx.y, bn = blockIdx.x;
    const int m0 = (wid >> 2) * 64, n0 = (wid & 3) * 32;

    const float* Ag0 = A + (size_t)(bm * 128) * K;
    const float* Bg0 = B + (size_t)(bn * 128) * K;

    const int lr = tid >> 3, lc = tid & 7;     // loader: 32 rows x 8 chunks

    float acc[4][4][4];
    #pragma unroll
    for (int i = 0; i < 4; i++)
        #pragma unroll
        for (int j = 0; j < 4; j++)
            #pragma unroll
            for (int v = 0; v < 4; v++) acc[i][j][v] = 0.f;

    const int KT = K >> 5;

    auto load_stage = [&](int s, int kt) {
        uint32_t base = sb + s * STAGEB;
        const float* Ag = Ag0 + kt * 32;
        const float* Bg = Bg0 + kt * 32;
        #pragma unroll
        for (int j = 0; j < 4; j++) {
            int r = lr + j * 32;
            CP_ASYNC16(base +        r * RSB + lc * 16, Ag + (size_t)r * K + lc * 4);
            CP_ASYNC16(base + MATB + r * RSB + lc * 16, Bg + (size_t)r * K + lc * 4);
        }
        CP_COMMIT();
    };

    load_stage(0, 0);
    if (KT > 1) load_stage(1, 1); else CP_COMMIT();

    // ldmatrix per-thread address offsets (A: x4 quadrants m0k0,m8k0,m0k4,m8k4; B: x2)
    const int aj = lane >> 3;                          // 0..3
    const uint32_t aoff = (uint32_t)(((lane & 7) + (aj & 1) * 8) * RSB + (aj >> 1) * 16);
    const uint32_t boff = (uint32_t)((lane & 7) * RSB + ((lane >> 3) & 1) * 16);

    int stage = 0;
    for (int kt = 0; kt < KT; kt++) {
        CP_WAIT(1);
        __syncthreads();
        if (kt + 2 < KT) {
            int s = stage + 2; if (s >= NSTAGE) s -= NSTAGE;
            load_stage(s, kt + 2);
        } else CP_COMMIT();

        uint32_t abase = sb + stage * STAGEB + m0 * RSB + aoff;
        uint32_t bbase = sb + stage * STAGEB + MATB + n0 * RSB + boff;
        #pragma unroll
        for (int ks = 0; ks < 4; ks++) {
            uint32_t af[4][4], bf[4][2];
            #pragma unroll
            for (int im = 0; im < 4; im++)
                ldsm_x4(af[im], abase + im * (16 * RSB) + ks * 32);
            #pragma unroll
            for (int in = 0; in < 4; in++)
                ldsm_x2(bf[in], bbase + in * (8 * RSB) + ks * 32);
            #pragma unroll
            for (int im = 0; im < 4; im++)
                #pragma unroll
                for (int in = 0; in < 4; in++)
                    mma_tf32(acc[im][in], af[im], bf[in]);
        }
        if (++stage == NSTAGE) stage = 0;
    }

    const int crow = lane >> 2, ccol = (lane & 3) * 2;
    #pragma unroll
    for (int im = 0; im < 4; im++) {
        #pragma unroll
        for (int in = 0; in < 4; in++) {
            int col = bn * 128 + n0 + in * 8 + ccol;
            float b0 = bias[col], b1 = bias[col + 1];
            #pragma unroll
            for (int half = 0; half < 2; half++) {
                int row = bm * 128 + m0 + im * 16 + crow + half * 8;
                float v0 = acc[im][in][half * 2 + 0] + b0;
                float v1 = acc[im][in][half * 2 + 1] + b1;
                *(float2*)(C + (size_t)row * N + col) = make_float2(v0, v1);
            }
        }
    }
}

// ---------------- 64x64 tf32 variant (128 threads, 2x2 warps of 32x32) ----------
#define MATB64    (64 * RSB)              // 9216
#define STAGEB64  (2 * MATB64)            // 18432
#define GEMM_SMEM64 (NSTAGE * STAGEB64)   // 55296 -> 4 CTAs/SM

template <bool RELU, bool ROUND>
__global__ void __launch_bounds__(128, 4)
gemm_t64(const float* __restrict__ A, const float* __restrict__ B,
         const float* __restrict__ bias, float* __restrict__ C, int N, int K) {
    extern __shared__ char dsm[];
    const uint32_t sb = smem_u32(dsm);

    const int tid = threadIdx.x, wid = tid >> 5, lane = tid & 31;
    const int bm = blockIdx.y, bn = blockIdx.x;
    const int m0 = (wid >> 1) * 32, n0 = (wid & 1) * 32;

    const float* Ag0 = A + (size_t)(bm * 64) * K;
    const float* Bg0 = B + (size_t)(bn * 64) * K;

    const int lr = tid >> 3, lc = tid & 7;     // 16 rows x 8 chunks per pass

    float acc[2][4][4];
    #pragma unroll
    for (int i = 0; i < 2; i++)
        #pragma unroll
        for (int j = 0; j < 4; j++)
            #pragma unroll
            for (int v = 0; v < 4; v++) acc[i][j][v] = 0.f;

    const int KT = K >> 5;

    auto load_stage = [&](int s, int kt) {
        uint32_t base = sb + s * STAGEB64;
        const float* Ag = Ag0 + kt * 32;
        const float* Bg = Bg0 + kt * 32;
        #pragma unroll
        for (int j = 0; j < 4; j++) {
            int r = lr + j * 16;
            CP_ASYNC16(base +          r * RSB + lc * 16, Ag + (size_t)r * K + lc * 4);
            CP_ASYNC16(base + MATB64 + r * RSB + lc * 16, Bg + (size_t)r * K + lc * 4);
        }
        CP_COMMIT();
    };

    load_stage(0, 0);
    if (KT > 1) load_stage(1, 1); else CP_COMMIT();

    const int aj = lane >> 3;
    const uint32_t aoff = (uint32_t)(((lane & 7) + (aj & 1) * 8) * RSB + (aj >> 1) * 16);
    const uint32_t boff = (uint32_t)((lane & 7) * RSB + ((lane >> 3) & 1) * 16);

    int stage = 0;
    for (int kt = 0; kt < KT; kt++) {
        CP_WAIT(1);
        __syncthreads();
        if (kt + 2 < KT) {
            int s = stage + 2; if (s >= NSTAGE) s -= NSTAGE;
            load_stage(s, kt + 2);
        } else CP_COMMIT();

        uint32_t abase = sb + stage * STAGEB64 + m0 * RSB + aoff;
        uint32_t bbase = sb + stage * STAGEB64 + MATB64 + n0 * RSB + boff;
        #pragma unroll
        for (int ks = 0; ks < 4; ks++) {
            uint32_t af[2][4], bf[4][2];
            #pragma unroll
            for (int im = 0; im < 2; im++)
                ldsm_x4(af[im], abase + im * (16 * RSB) + ks * 32);
            #pragma unroll
            for (int in = 0; in < 4; in++)
                ldsm_x2(bf[in], bbase + in * (8 * RSB) + ks * 32);
            #pragma unroll
            for (int im = 0; im < 2; im++)
                #pragma unroll
                for (int in = 0; in < 4; in++)
                    mma_tf32(acc[im][in], af[im], bf[in]);
        }
        if (++stage == NSTAGE) stage = 0;
    }

    const int crow = lane >> 2, ccol = (lane & 3) * 2;
    #pragma unroll
    for (int im = 0; im < 2; im++) {
        #pragma unroll
        for (int in = 0; in < 4; in++) {
            int col = bn * 64 + n0 + in * 8 + ccol;
            float b0 = bias[col], b1 = bias[col + 1];
            #pragma unroll
            for (int half = 0; half < 2; half++) {
                int row = bm * 64 + m0 + im * 16 + crow + half * 8;
                float v0 = acc[im][in][half * 2 + 0] + b0;
                float v1 = acc[im][in][half * 2 + 1] + b1;
                if (RELU)  { v0 = fmaxf(v0, 0.f); v1 = fmaxf(v1, 0.f); }
                if (ROUND) { v0 = rtf32(v0); v1 = rtf32(v1); }
                *(float2*)(C + (size_t)row * N + col) = make_float2(v0, v1);
            }
        }
    }
}

// ---------------- launch ----------------
extern "C" void kernel_launch(void* const* d_in, const int* in_sizes, int n_in,
                              void* d_out, int out_size) {
    const float* exp_e = (const float*)d_in[0];
    const float* per_e = (const float*)d_in[1];
    const float* ipw   = (const float*)d_in[2];
    const float* ipb   = (const float*)d_in[3];
    const float* opw   = (const float*)d_in[4];
    const float* opb   = (const float*)d_in[5];
    const float* ln0g  = (const float*)d_in[6];
    const float* ln0b  = (const float*)d_in[7];
    const float* ln1g  = (const float*)d_in[8];
    const float* ln1b  = (const float*)d_in[9];
    const float* ln2g  = (const float*)d_in[10];
    const float* ln2b  = (const float*)d_in[11];
    const float* w1    = (const float*)d_in[12];
    const float* b1    = (const float*)d_in[13];
    const float* w2    = (const float*)d_in[14];
    const float* b2    = (const float*)d_in[15];
    const int*   adj   = (const int*)d_in[16];
    float* out = (float*)d_out;

    float *xin, *qkv, *att, *prj, *x1, *hh, *ff, *wq, *wo, *wr1, *wr2;
    cudaGetSymbolAddress((void**)&xin, g_xin);
    cudaGetSymbolAddress((void**)&qkv, g_qkv);
    cudaGetSymbolAddress((void**)&att, g_att);
    cudaGetSymbolAddress((void**)&prj, g_prj);
    cudaGetSymbolAddress((void**)&x1,  g_x1);
    cudaGetSymbolAddress((void**)&hh,  g_hh);
    cudaGetSymbolAddress((void**)&ff,  g_ff);
    cudaGetSymbolAddress((void**)&wq,  g_wq);
    cudaGetSymbolAddress((void**)&wo,  g_wo);
    cudaGetSymbolAddress((void**)&wr1, g_w1);
    cudaGetSymbolAddress((void**)&wr2, g_w2);

    cudaFuncSetAttribute(gemm_t128, cudaFuncAttributeMaxDynamicSharedMemorySize, GEMM_SMEM);
    cudaFuncSetAttribute(gemm_t64<false, false>, cudaFuncAttributeMaxDynamicSharedMemorySize, GEMM_SMEM64);
    cudaFuncSetAttribute(gemm_t64<true,  true >, cudaFuncAttributeMaxDynamicSharedMemorySize, GEMM_SMEM64);

    // weights -> tf32-rounded copies
    round4_kernel<<<dim3(1728, 4), 256>>>(
        ipw, wq,  QKVD * DIM / 4,
        opw, wo,  DIM * DIM / 4,
        w1,  wr1, FFD * DIM / 4,
        w2,  wr2, DIM * FFD / 4);
    // neighbor lists
    build_nbr_kernel<<<SQ, 256>>>(adj);
    // x_in = LN0(exp + pert), tf32-rounded
    add_ln_kernel<<<SQ, 256>>>(exp_e, per_e, ln0g, ln0b, xin, 1);
    // qkv = x_in @ ipw^T + ipb   (288 CTAs, 128x128, 2 CTAs/SM)
    gemm_t128<<<dim3(QKVD / 128, SQ / 128), 256, GEMM_SMEM>>>(xin, wq, ipb, qkv, QKVD, DIM);
    // sparse attention -> tf32-rounded att
    attn_kernel<<<SQ, 192>>>();
    // prj = att @ opw^T + opb   (384 CTAs, 64x64, 4 CTAs/SM)
    gemm_t64<false, false><<<dim3(DIM / 64, SQ / 64), 128, GEMM_SMEM64>>>(att, wo, opb, prj, DIM, DIM);
    // x1 = LN1(prj + xin), tf32-rounded
    add_ln_kernel<<<SQ, 256>>>(prj, xin, ln1g, ln1b, x1, 1);
    // hh = relu(x1 @ w1^T + b1), tf32-rounded   (192 CTAs)
    gemm_t64<true, true><<<dim3(FFD / 64, SQ / 64), 128, GEMM_SMEM64>>>(x1, wr1, b1, hh, FFD, DIM);
    // ff = hh @ w2^T + b2   (384 CTAs)
    gemm_t64<false, false><<<dim3(DIM / 64, SQ / 64), 128, GEMM_SMEM64>>>(hh, wr2, b2, ff, DIM, FFD);
    // out = LN2(x1 + ff), full fp32
    add_ln_kernel<<<SQ, 256>>>(x1, ff, ln2g, ln2b, out, 0);
}